// round 1
// baseline (speedup 1.0000x reference)
#include <cuda_runtime.h>

// LSTM cell: B=16384, D=H=1024.
// gates[g][m][n] = sum_k A[m][k]*Wg[n][k] over k=0..2047 (A = [x | h], Wg = [Wg_x | Wg_h])
// epilogue: i,f,o raw; g=tanh; c = g*i + c_prev*f; h = o*tanh(c)
//
// Block computes a 64x64 tile of ALL FOUR gates (fused epilogue, no scratch).
// Inner product uses packed fma.rn.f32x2 (2 FMA/instr) — sm_100+ PTX only.

#define BDIM 16384
#define HDIM 1024
#define KTOT 2048

__device__ __forceinline__ unsigned long long pk2(float v) {
    unsigned long long r;
    asm("mov.b64 %0, {%1, %1};" : "=l"(r) : "f"(v));
    return r;
}
__device__ __forceinline__ float2 up2(unsigned long long v) {
    float2 r;
    asm("mov.b64 {%0, %1}, %2;" : "=f"(r.x), "=f"(r.y) : "l"(v));
    return r;
}
#define FMA2(d, a, b) asm("fma.rn.f32x2 %0, %1, %2, %0;" : "+l"(d) : "l"(a), "l"(b))

__global__ __launch_bounds__(256)
void lstm_fused_kernel(
    const float* __restrict__ x, const float* __restrict__ h,
    const float* __restrict__ c_prev,
    const float* __restrict__ Wix, const float* __restrict__ Wfx,
    const float* __restrict__ Wcx, const float* __restrict__ Wox,
    const float* __restrict__ Wih, const float* __restrict__ Wfh,
    const float* __restrict__ Wch, const float* __restrict__ Woh,
    const float* __restrict__ bix, const float* __restrict__ bfx,
    const float* __restrict__ bcx, const float* __restrict__ box_,
    const float* __restrict__ bih, const float* __restrict__ bfh,
    const float* __restrict__ bch, const float* __restrict__ boh,
    float* __restrict__ out)
{
    __shared__ __align__(16) float As[16][68];        // [k][m], padded
    __shared__ __align__(16) float Bs[4][16][68];     // [gate][k][n], padded

    const int tid = threadIdx.x;
    const int tx = tid & 15;          // n sub-tile
    const int ty = tid >> 4;          // m sub-tile
    const int n0 = blockIdx.x * 64;
    const int m0 = blockIdx.y * 64;

    // loader mapping: each thread loads one float4 per tile per matrix
    const int ldr = tid >> 2;         // row 0..63
    const int ldk = (tid & 3) * 4;    // k offset 0,4,8,12

    unsigned long long acc[4][4][2];  // [gate][m][packed n-pair]
    #pragma unroll
    for (int g = 0; g < 4; g++)
        #pragma unroll
        for (int i = 0; i < 4; i++) { acc[g][i][0] = 0ull; acc[g][i][1] = 0ull; }

    float4 pa, pb0, pb1, pb2, pb3;
    // prefetch tile 0 (k=0 -> x-side weights)
    {
        pa  = *(const float4*)(x   + (size_t)(m0 + ldr) * 1024 + ldk);
        pb0 = *(const float4*)(Wix + (size_t)(n0 + ldr) * 1024 + ldk);
        pb1 = *(const float4*)(Wfx + (size_t)(n0 + ldr) * 1024 + ldk);
        pb2 = *(const float4*)(Wcx + (size_t)(n0 + ldr) * 1024 + ldk);
        pb3 = *(const float4*)(Wox + (size_t)(n0 + ldr) * 1024 + ldk);
    }

    const int NT = KTOT / 16;  // 128 tiles
    for (int t = 0; t < NT; t++) {
        // store prefetched tile into smem (transposed to [k][row])
        As[ldk + 0][ldr] = pa.x;  As[ldk + 1][ldr] = pa.y;
        As[ldk + 2][ldr] = pa.z;  As[ldk + 3][ldr] = pa.w;
        Bs[0][ldk + 0][ldr] = pb0.x; Bs[0][ldk + 1][ldr] = pb0.y;
        Bs[0][ldk + 2][ldr] = pb0.z; Bs[0][ldk + 3][ldr] = pb0.w;
        Bs[1][ldk + 0][ldr] = pb1.x; Bs[1][ldk + 1][ldr] = pb1.y;
        Bs[1][ldk + 2][ldr] = pb1.z; Bs[1][ldk + 3][ldr] = pb1.w;
        Bs[2][ldk + 0][ldr] = pb2.x; Bs[2][ldk + 1][ldr] = pb2.y;
        Bs[2][ldk + 2][ldr] = pb2.z; Bs[2][ldk + 3][ldr] = pb2.w;
        Bs[3][ldk + 0][ldr] = pb3.x; Bs[3][ldk + 1][ldr] = pb3.y;
        Bs[3][ldk + 2][ldr] = pb3.z; Bs[3][ldk + 3][ldr] = pb3.w;
        __syncthreads();

        // prefetch next tile while computing this one
        if (t + 1 < NT) {
            const int kt = (t + 1) * 16;
            const bool xs = (kt < 1024);
            const int  kk = kt & 1023;
            const float* A  = xs ? x   : h;
            const float* W0 = xs ? Wix : Wih;
            const float* W1 = xs ? Wfx : Wfh;
            const float* W2 = xs ? Wcx : Wch;
            const float* W3 = xs ? Wox : Woh;
            pa  = *(const float4*)(A  + (size_t)(m0 + ldr) * 1024 + kk + ldk);
            pb0 = *(const float4*)(W0 + (size_t)(n0 + ldr) * 1024 + kk + ldk);
            pb1 = *(const float4*)(W1 + (size_t)(n0 + ldr) * 1024 + kk + ldk);
            pb2 = *(const float4*)(W2 + (size_t)(n0 + ldr) * 1024 + kk + ldk);
            pb3 = *(const float4*)(W3 + (size_t)(n0 + ldr) * 1024 + kk + ldk);
        }

        #pragma unroll
        for (int k = 0; k < 16; k++) {
            const float4 av = *(const float4*)&As[k][ty * 4];
            unsigned long long a2_0 = pk2(av.x);
            unsigned long long a2_1 = pk2(av.y);
            unsigned long long a2_2 = pk2(av.z);
            unsigned long long a2_3 = pk2(av.w);
            #pragma unroll
            for (int g = 0; g < 4; g++) {
                const ulonglong2 bv = *(const ulonglong2*)&Bs[g][k][tx * 4];
                FMA2(acc[g][0][0], a2_0, bv.x); FMA2(acc[g][0][1], a2_0, bv.y);
                FMA2(acc[g][1][0], a2_1, bv.x); FMA2(acc[g][1][1], a2_1, bv.y);
                FMA2(acc[g][2][0], a2_2, bv.x); FMA2(acc[g][2][1], a2_2, bv.y);
                FMA2(acc[g][3][0], a2_3, bv.x); FMA2(acc[g][3][1], a2_3, bv.y);
            }
        }
        __syncthreads();
    }

    // ---- epilogue: biases + LSTM nonlinearity, fully fused ----
    const int nb = n0 + tx * 4;
    float bi4[4], bf4[4], bc4[4], bo4[4];
    #pragma unroll
    for (int j = 0; j < 4; j++) {
        const int n = nb + j;
        bi4[j] = bix[n] + bih[n];
        bf4[j] = bfx[n] + bfh[n];
        bc4[j] = bcx[n] + bch[n];
        bo4[j] = box_[n] + boh[n];
    }

    #pragma unroll
    for (int i = 0; i < 4; i++) {
        const int m = m0 + ty * 4 + i;
        const size_t base = (size_t)m * 1024 + nb;

        float2 iv01 = up2(acc[0][i][0]), iv23 = up2(acc[0][i][1]);
        float2 fv01 = up2(acc[1][i][0]), fv23 = up2(acc[1][i][1]);
        float2 gv01 = up2(acc[2][i][0]), gv23 = up2(acc[2][i][1]);
        float2 ov01 = up2(acc[3][i][0]), ov23 = up2(acc[3][i][1]);
        float iv[4] = {iv01.x, iv01.y, iv23.x, iv23.y};
        float fv[4] = {fv01.x, fv01.y, fv23.x, fv23.y};
        float gv[4] = {gv01.x, gv01.y, gv23.x, gv23.y};
        float ov[4] = {ov01.x, ov01.y, ov23.x, ov23.y};

        const float4 cp4 = *(const float4*)(c_prev + base);
        const float cp[4] = {cp4.x, cp4.y, cp4.z, cp4.w};

        float4 hv, cv;
        #pragma unroll
        for (int j = 0; j < 4; j++) {
            const float I = iv[j] + bi4[j];
            const float F = fv[j] + bf4[j];
            const float G = tanhf(gv[j] + bc4[j]);
            const float O = ov[j] + bo4[j];
            const float c = G * I + cp[j] * F;
            (&cv.x)[j] = c;
            (&hv.x)[j] = O * tanhf(c);
        }
        *(float4*)(out + base) = hv;                                      // h_next
        *(float4*)(out + (size_t)BDIM * HDIM + base) = cv;                // c_next
    }
}

extern "C" void kernel_launch(void* const* d_in, const int* in_sizes, int n_in,
                              void* d_out, int out_size) {
    const float* x      = (const float*)d_in[0];
    const float* h      = (const float*)d_in[1];
    const float* c_prev = (const float*)d_in[2];
    const float* Wix = (const float*)d_in[3];  const float* bix = (const float*)d_in[4];
    const float* Wfx = (const float*)d_in[5];  const float* bfx = (const float*)d_in[6];
    const float* Wcx = (const float*)d_in[7];  const float* bcx = (const float*)d_in[8];
    const float* Wox = (const float*)d_in[9];  const float* box_ = (const float*)d_in[10];
    const float* Wih = (const float*)d_in[11]; const float* bih = (const float*)d_in[12];
    const float* Wfh = (const float*)d_in[13]; const float* bfh = (const float*)d_in[14];
    const float* Wch = (const float*)d_in[15]; const float* bch = (const float*)d_in[16];
    const float* Woh = (const float*)d_in[17]; const float* boh = (const float*)d_in[18];
    float* out = (float*)d_out;

    dim3 grid(HDIM / 64, BDIM / 64);   // (16, 256)
    lstm_fused_kernel<<<grid, 256>>>(x, h, c_prev,
        Wix, Wfx, Wcx, Wox, Wih, Wfh, Wch, Woh,
        bix, bfx, bcx, box_, bih, bfh, bch, boh, out);
}

// round 4
// speedup vs baseline: 2.3196x; 2.3196x over previous
#include <cuda_runtime.h>
#include <cuda_bf16.h>
#include <cstdint>

#define BDIM 16384
#define HDIM 1024
#define KTOT 2048
#define MT   128            // CTA M tile
#define NPT  256            // CTA permuted-N tile (4 gates x 64)
#define BK   32             // K per stage
#define NITER (KTOT / BK)   // 64
#define THREADS 256

// padded smem row: 32 + 8 bf16 = 80 bytes (20 words -> conflict-free frags)
#define ROWB 80
#define ASZ  (MT  * ROWB)   // 10240
#define BSZ  (NPT * ROWB)   // 20480
#define STG  (2 * ASZ + 2 * BSZ)   // 61440
#define NSTAGE 3
#define SMEM_TOTAL (NSTAGE * STG)  // 184320

// ---------------- scratch (device globals) ----------------
__device__ __nv_bfloat16 g_Ahi[(size_t)BDIM * KTOT];
__device__ __nv_bfloat16 g_Alo[(size_t)BDIM * KTOT];
__device__ __nv_bfloat16 g_Whi[(size_t)4 * HDIM * KTOT];  // [ntile16][gate4][64][K]
__device__ __nv_bfloat16 g_Wlo[(size_t)4 * HDIM * KTOT];

// ---------------- helpers ----------------
__device__ __forceinline__ uint32_t smem_u32(const void* p) {
    uint32_t a;
    asm("{ .reg .u64 t; cvta.to.shared.u64 t, %1; cvt.u32.u64 %0, t; }" : "=r"(a) : "l"(p));
    return a;
}
#define CP_ASYNC16(dst, src) \
    asm volatile("cp.async.cg.shared.global [%0], [%1], 16;" :: "r"((uint32_t)(dst)), "l"(src) : "memory")
#define CP_COMMIT() asm volatile("cp.async.commit_group;" ::: "memory")
#define CP_WAIT(n)  asm volatile("cp.async.wait_group %0;" :: "n"(n) : "memory")

__device__ __forceinline__ void mma16816(float* d, const uint32_t* a, const uint32_t* b) {
    asm volatile("mma.sync.aligned.m16n8k16.row.col.f32.bf16.bf16.f32 "
        "{%0,%1,%2,%3}, {%4,%5,%6,%7}, {%8,%9}, {%0,%1,%2,%3};"
        : "+f"(d[0]), "+f"(d[1]), "+f"(d[2]), "+f"(d[3])
        : "r"(a[0]), "r"(a[1]), "r"(a[2]), "r"(a[3]), "r"(b[0]), "r"(b[1]));
}
__device__ __forceinline__ uint32_t lds32(uint32_t a) {
    uint32_t v; asm volatile("ld.shared.b32 %0, [%1];" : "=r"(v) : "r"(a)); return v;
}

// ---------------- conversion prepass ----------------
__device__ __forceinline__ void cvt8(const float* v, uint4& uh, uint4& ul) {
    uint32_t hw[4], lw[4];
    #pragma unroll
    for (int p = 0; p < 4; p++) {
        float a = v[2 * p], b = v[2 * p + 1];
        __nv_bfloat16 ah = __float2bfloat16(a), bh = __float2bfloat16(b);
        __nv_bfloat16 al = __float2bfloat16(a - __bfloat162float(ah));
        __nv_bfloat16 bl = __float2bfloat16(b - __bfloat162float(bh));
        hw[p] = (uint32_t)__bfloat16_as_ushort(ah) | ((uint32_t)__bfloat16_as_ushort(bh) << 16);
        lw[p] = (uint32_t)__bfloat16_as_ushort(al) | ((uint32_t)__bfloat16_as_ushort(bl) << 16);
    }
    uh = make_uint4(hw[0], hw[1], hw[2], hw[3]);
    ul = make_uint4(lw[0], lw[1], lw[2], lw[3]);
}

__global__ __launch_bounds__(256)
void conv_A_kernel(const float* __restrict__ x, const float* __restrict__ h) {
    size_t i = ((size_t)blockIdx.x * 256 + threadIdx.x) * 8;
    int m = (int)(i >> 11);
    int k = (int)(i & 2047);
    const float* src = (k < 1024) ? (x + (size_t)m * 1024 + k)
                                  : (h + (size_t)m * 1024 + (k - 1024));
    float v[8];
    *(float4*)(v)     = *(const float4*)(src);
    *(float4*)(v + 4) = *(const float4*)(src + 4);
    uint4 uh, ul;
    cvt8(v, uh, ul);
    *(uint4*)(g_Ahi + i) = uh;
    *(uint4*)(g_Alo + i) = ul;
}

__global__ __launch_bounds__(256)
void conv_W_kernel(const float* __restrict__ Wix, const float* __restrict__ Wfx,
                   const float* __restrict__ Wcx, const float* __restrict__ Wox,
                   const float* __restrict__ Wih, const float* __restrict__ Wfh,
                   const float* __restrict__ Wch, const float* __restrict__ Woh) {
    size_t i = ((size_t)blockIdx.x * 256 + threadIdx.x) * 8;
    int rp = (int)(i >> 11);
    int k  = (int)(i & 2047);
    int ntile = rp >> 8, rem = rp & 255, g = rem >> 6, nl = rem & 63;
    int n = ntile * 64 + nl;
    const float* Wx; const float* Wh;
    if      (g == 0) { Wx = Wix; Wh = Wih; }
    else if (g == 1) { Wx = Wfx; Wh = Wfh; }
    else if (g == 2) { Wx = Wcx; Wh = Wch; }
    else             { Wx = Wox; Wh = Woh; }
    const float* src = (k < 1024) ? (Wx + (size_t)n * 1024 + k)
                                  : (Wh + (size_t)n * 1024 + (k - 1024));
    float v[8];
    *(float4*)(v)     = *(const float4*)(src);
    *(float4*)(v + 4) = *(const float4*)(src + 4);
    uint4 uh, ul;
    cvt8(v, uh, ul);
    *(uint4*)(g_Whi + i) = uh;
    *(uint4*)(g_Wlo + i) = ul;
}

// ---------------- main GEMM + fused LSTM epilogue ----------------
__global__ __launch_bounds__(THREADS, 1)
void lstm_mma_kernel(const float* __restrict__ c_prev,
                     const float* __restrict__ bix, const float* __restrict__ bih,
                     const float* __restrict__ bfx, const float* __restrict__ bfh,
                     const float* __restrict__ bcx, const float* __restrict__ bch,
                     const float* __restrict__ box_, const float* __restrict__ boh,
                     float* __restrict__ out) {
    extern __shared__ __align__(128) char smem[];
    const uint32_t su = smem_u32(smem);
    const int tid = threadIdx.x;
    const int wid = tid >> 5, lane = tid & 31;
    const int g = lane >> 2, tq = lane & 3;
    const int warp_m = wid >> 2;          // 0..1
    const int warp_n = wid & 3;           // 0..3 == gate
    const int m0 = blockIdx.y * MT;
    const int bx = blockIdx.x;            // n-tile
    const int n0 = bx * 64;

    const __nv_bfloat16* Abase_h = g_Ahi + (size_t)m0 * KTOT;
    const __nv_bfloat16* Abase_l = g_Alo + (size_t)m0 * KTOT;
    const __nv_bfloat16* Wbase_h = g_Whi + (size_t)bx * NPT * KTOT;
    const __nv_bfloat16* Wbase_l = g_Wlo + (size_t)bx * NPT * KTOT;

    float acc[4][8][4];
    #pragma unroll
    for (int a = 0; a < 4; a++)
        #pragma unroll
        for (int b = 0; b < 8; b++)
            #pragma unroll
            for (int c = 0; c < 4; c++) acc[a][b][c] = 0.f;

    // ---- pipeline loads ----
    auto load_stage = [&](int t, int s) {
        const int k0 = t * BK;
        const uint32_t st = su + (uint32_t)s * STG;
        #pragma unroll
        for (int rep = 0; rep < 2; rep++) {                 // A hi/lo: 512 chunks each
            int i = tid + rep * 256;
            int row = i >> 2, cc = i & 3;
            const __nv_bfloat16* sh = Abase_h + (size_t)row * KTOT + k0 + cc * 8;
            const __nv_bfloat16* sl = Abase_l + (size_t)row * KTOT + k0 + cc * 8;
            uint32_t off = (uint32_t)row * ROWB + cc * 16;
            CP_ASYNC16(st + off,        sh);
            CP_ASYNC16(st + ASZ + off,  sl);
        }
        #pragma unroll
        for (int rep = 0; rep < 4; rep++) {                 // B hi/lo: 1024 chunks each
            int i = tid + rep * 256;
            int row = i >> 2, cc = i & 3;
            const __nv_bfloat16* sh = Wbase_h + (size_t)row * KTOT + k0 + cc * 8;
            const __nv_bfloat16* sl = Wbase_l + (size_t)row * KTOT + k0 + cc * 8;
            uint32_t off = (uint32_t)row * ROWB + cc * 16;
            CP_ASYNC16(st + 2 * ASZ + off,        sh);
            CP_ASYNC16(st + 2 * ASZ + BSZ + off,  sl);
        }
        CP_COMMIT();
    };

    load_stage(0, 0);
    load_stage(1, 1);

    // frag base offsets (bytes within a stage)
    const uint32_t aRow = (uint32_t)(warp_m * 64 + g);
    const uint32_t bRow = (uint32_t)(warp_n * 64 + g);

    #pragma unroll 1
    for (int t = 0; t < NITER; t++) {
        if (t < NITER - 1) CP_WAIT(1); else CP_WAIT(0);
        __syncthreads();
        if (t + 2 < NITER) load_stage(t + 2, (t + 2) % NSTAGE);

        const uint32_t st = su + (uint32_t)(t % NSTAGE) * STG;
        const uint32_t uAh = st, uAl = st + ASZ, uBh = st + 2 * ASZ, uBl = st + 2 * ASZ + BSZ;

        #pragma unroll
        for (int kt = 0; kt < 2; kt++) {
            const uint32_t kb = (uint32_t)(kt * 32 + tq * 4);
            uint32_t afh[4][4], afl[4][4], bfh[8][2], bfl[8][2];
            #pragma unroll
            for (int tm = 0; tm < 4; tm++) {
                uint32_t r = (aRow + 16 * tm) * ROWB + kb;
                afh[tm][0] = lds32(uAh + r);        afh[tm][1] = lds32(uAh + r + 8 * ROWB);
                afh[tm][2] = lds32(uAh + r + 16);   afh[tm][3] = lds32(uAh + r + 8 * ROWB + 16);
                afl[tm][0] = lds32(uAl + r);        afl[tm][1] = lds32(uAl + r + 8 * ROWB);
                afl[tm][2] = lds32(uAl + r + 16);   afl[tm][3] = lds32(uAl + r + 8 * ROWB + 16);
            }
            #pragma unroll
            for (int tn = 0; tn < 8; tn++) {
                uint32_t r = (bRow + 8 * tn) * ROWB + kb;
                bfh[tn][0] = lds32(uBh + r);  bfh[tn][1] = lds32(uBh + r + 16);
                bfl[tn][0] = lds32(uBl + r);  bfl[tn][1] = lds32(uBl + r + 16);
            }
            #pragma unroll
            for (int tm = 0; tm < 4; tm++)
                #pragma unroll
                for (int tn = 0; tn < 8; tn++) {
                    mma16816(acc[tm][tn], afh[tm], bfh[tn]);
                    mma16816(acc[tm][tn], afh[tm], bfl[tn]);
                    mma16816(acc[tm][tn], afl[tm], bfh[tn]);
                }
        }
    }
    __syncthreads();

    // ---- epilogue: combine 4 gates through smem, fuse LSTM math ----
    // layout: eg[warp_m][gate][64][68] floats ; biases after
    float* eg   = (float*)smem;
    float* bsum = (float*)(smem + 2 * 4 * 64 * 68 * 4);   // 139264
    const uint32_t egBase = (uint32_t)((warp_m * 4 + warp_n) * 64 * 68);

    #pragma unroll
    for (int tm = 0; tm < 4; tm++)
        #pragma unroll
        for (int tn = 0; tn < 8; tn++) {
            uint32_t r0 = egBase + (uint32_t)(16 * tm + g) * 68 + 8 * tn + tq * 2;
            eg[r0]            = acc[tm][tn][0];
            eg[r0 + 1]        = acc[tm][tn][1];
            eg[r0 + 8 * 68]     = acc[tm][tn][2];
            eg[r0 + 8 * 68 + 1] = acc[tm][tn][3];
        }
    if (tid < 64) {
        int n = n0 + tid;
        bsum[tid]       = bix[n] + bih[n];
        bsum[64 + tid]  = bfx[n] + bfh[n];
        bsum[128 + tid] = bcx[n] + bch[n];
        bsum[192 + tid] = box_[n] + boh[n];
    }
    __syncthreads();

    #pragma unroll
    for (int it = 0; it < 32; it++) {
        int idx = tid + it * 256;          // 0..8191
        int row = idx >> 6, col = idx & 63;
        int wm = row >> 6, r = row & 63;
        const float* base = eg + (size_t)wm * 4 * 64 * 68 + (size_t)r * 68 + col;
        float I = base[0]            + bsum[col];
        float F = base[64 * 68]      + bsum[64 + col];
        float G = tanhf(base[2 * 64 * 68] + bsum[128 + col]);
        float O = base[3 * 64 * 68]  + bsum[192 + col];
        size_t go = (size_t)(m0 + row) * HDIM + n0 + col;
        float cn = G * I + c_prev[go] * F;
        out[go] = O * tanhf(cn);
        out[(size_t)BDIM * HDIM + go] = cn;
    }
}

// ---------------- launch ----------------
extern "C" void kernel_launch(void* const* d_in, const int* in_sizes, int n_in,
                              void* d_out, int out_size) {
    const float* x      = (const float*)d_in[0];
    const float* h      = (const float*)d_in[1];
    const float* c_prev = (const float*)d_in[2];
    const float* Wix = (const float*)d_in[3];  const float* bix  = (const float*)d_in[4];
    const float* Wfx = (const float*)d_in[5];  const float* bfx  = (const float*)d_in[6];
    const float* Wcx = (const float*)d_in[7];  const float* bcx  = (const float*)d_in[8];
    const float* Wox = (const float*)d_in[9];  const float* box_ = (const float*)d_in[10];
    const float* Wih = (const float*)d_in[11]; const float* bih  = (const float*)d_in[12];
    const float* Wfh = (const float*)d_in[13]; const float* bfh  = (const float*)d_in[14];
    const float* Wch = (const float*)d_in[15]; const float* bch  = (const float*)d_in[16];
    const float* Woh = (const float*)d_in[17]; const float* boh  = (const float*)d_in[18];
    float* out = (float*)d_out;

    conv_A_kernel<<<BDIM * KTOT / 8 / 256, 256>>>(x, h);
    conv_W_kernel<<<4 * HDIM * KTOT / 8 / 256, 256>>>(Wix, Wfx, Wcx, Wox, Wih, Wfh, Wch, Woh);

    cudaFuncSetAttribute(lstm_mma_kernel, cudaFuncAttributeMaxDynamicSharedMemorySize, SMEM_TOTAL);
    dim3 grid(HDIM / 64, BDIM / MT);   // (16, 128)
    lstm_mma_kernel<<<grid, THREADS, SMEM_TOTAL>>>(c_prev,
        bix, bih, bfx, bfh, bcx, bch, box_, boh, out);
}

// round 9
// speedup vs baseline: 2.3841x; 1.0278x over previous
#include <cuda_runtime.h>
#include <cuda_bf16.h>
#include <cstdint>

#define BDIM 16384
#define HDIM 1024
#define KTOT 2048
#define MT   128            // CTA M tile
#define NPT  256            // CTA permuted-N tile (4 gates x 64)
#define BK   32             // K per stage
#define NITER (KTOT / BK)   // 64
#define THREADS 256

// padded smem row: 32 + 8 bf16 = 80 bytes (20 words -> conflict-free frags)
#define ROWB 80
#define ASZ  (MT  * ROWB)   // 10240
#define BSZ  (NPT * ROWB)   // 20480
#define STG  (2 * ASZ + 2 * BSZ)   // 61440
#define NSTAGE 3
#define SMEM_TOTAL (NSTAGE * STG)  // 184320

// ---------------- scratch (device globals) ----------------
__device__ __nv_bfloat16 g_Ahi[(size_t)BDIM * KTOT];
__device__ __nv_bfloat16 g_Alo[(size_t)BDIM * KTOT];
__device__ __nv_bfloat16 g_Whi[(size_t)4 * HDIM * KTOT];  // [ntile16][gate4][64][K]
__device__ __nv_bfloat16 g_Wlo[(size_t)4 * HDIM * KTOT];

// ---------------- helpers ----------------
__device__ __forceinline__ uint32_t smem_u32(const void* p) {
    uint32_t a;
    asm("{ .reg .u64 t; cvta.to.shared.u64 t, %1; cvt.u32.u64 %0, t; }" : "=r"(a) : "l"(p));
    return a;
}
#define CP_ASYNC16(dst, src) \
    asm volatile("cp.async.cg.shared.global [%0], [%1], 16;" :: "r"((uint32_t)(dst)), "l"(src) : "memory")
#define CP_COMMIT() asm volatile("cp.async.commit_group;" ::: "memory")
#define CP_WAIT(n)  asm volatile("cp.async.wait_group %0;" :: "n"(n) : "memory")

__device__ __forceinline__ void mma16816(float* d, const uint32_t* a, const uint32_t* b) {
    asm volatile("mma.sync.aligned.m16n8k16.row.col.f32.bf16.bf16.f32 "
        "{%0,%1,%2,%3}, {%4,%5,%6,%7}, {%8,%9}, {%0,%1,%2,%3};"
        : "+f"(d[0]), "+f"(d[1]), "+f"(d[2]), "+f"(d[3])
        : "r"(a[0]), "r"(a[1]), "r"(a[2]), "r"(a[3]), "r"(b[0]), "r"(b[1]));
}
__device__ __forceinline__ void ldsm4(uint32_t* r, uint32_t addr) {
    asm volatile("ldmatrix.sync.aligned.m8n8.x4.shared.b16 {%0,%1,%2,%3}, [%4];"
        : "=r"(r[0]), "=r"(r[1]), "=r"(r[2]), "=r"(r[3]) : "r"(addr));
}

// ---------------- conversion prepass ----------------
__device__ __forceinline__ void cvt8(const float* v, uint4& uh, uint4& ul) {
    uint32_t hw[4], lw[4];
    #pragma unroll
    for (int p = 0; p < 4; p++) {
        float a = v[2 * p], b = v[2 * p + 1];
        __nv_bfloat16 ah = __float2bfloat16(a), bh = __float2bfloat16(b);
        __nv_bfloat16 al = __float2bfloat16(a - __bfloat162float(ah));
        __nv_bfloat16 bl = __float2bfloat16(b - __bfloat162float(bh));
        hw[p] = (uint32_t)__bfloat16_as_ushort(ah) | ((uint32_t)__bfloat16_as_ushort(bh) << 16);
        lw[p] = (uint32_t)__bfloat16_as_ushort(al) | ((uint32_t)__bfloat16_as_ushort(bl) << 16);
    }
    uh = make_uint4(hw[0], hw[1], hw[2], hw[3]);
    ul = make_uint4(lw[0], lw[1], lw[2], lw[3]);
}

__global__ __launch_bounds__(256)
void conv_A_kernel(const float* __restrict__ x, const float* __restrict__ h) {
    size_t i = ((size_t)blockIdx.x * 256 + threadIdx.x) * 8;
    int m = (int)(i >> 11);
    int k = (int)(i & 2047);
    const float* src = (k < 1024) ? (x + (size_t)m * 1024 + k)
                                  : (h + (size_t)m * 1024 + (k - 1024));
    float v[8];
    *(float4*)(v)     = *(const float4*)(src);
    *(float4*)(v + 4) = *(const float4*)(src + 4);
    uint4 uh, ul;
    cvt8(v, uh, ul);
    *(uint4*)(g_Ahi + i) = uh;
    *(uint4*)(g_Alo + i) = ul;
}

__global__ __launch_bounds__(256)
void conv_W_kernel(const float* __restrict__ Wix, const float* __restrict__ Wfx,
                   const float* __restrict__ Wcx, const float* __restrict__ Wox,
                   const float* __restrict__ Wih, const float* __restrict__ Wfh,
                   const float* __restrict__ Wch, const float* __restrict__ Woh) {
    size_t i = ((size_t)blockIdx.x * 256 + threadIdx.x) * 8;
    int rp = (int)(i >> 11);
    int k  = (int)(i & 2047);
    int ntile = rp >> 8, rem = rp & 255, g = rem >> 6, nl = rem & 63;
    int n = ntile * 64 + nl;
    const float* Wx; const float* Wh;
    if      (g == 0) { Wx = Wix; Wh = Wih; }
    else if (g == 1) { Wx = Wfx; Wh = Wfh; }
    else if (g == 2) { Wx = Wcx; Wh = Wch; }
    else             { Wx = Wox; Wh = Woh; }
    const float* src = (k < 1024) ? (Wx + (size_t)n * 1024 + k)
                                  : (Wh + (size_t)n * 1024 + (k - 1024));
    float v[8];
    *(float4*)(v)     = *(const float4*)(src);
    *(float4*)(v + 4) = *(const float4*)(src + 4);
    uint4 uh, ul;
    cvt8(v, uh, ul);
    *(uint4*)(g_Whi + i) = uh;
    *(uint4*)(g_Wlo + i) = ul;
}

// ---------------- main GEMM + fused LSTM epilogue ----------------
__global__ __launch_bounds__(THREADS, 1)
void lstm_mma_kernel(const float* __restrict__ c_prev,
                     const float* __restrict__ bix, const float* __restrict__ bih,
                     const float* __restrict__ bfx, const float* __restrict__ bfh,
                     const float* __restrict__ bcx, const float* __restrict__ bch,
                     const float* __restrict__ box_, const float* __restrict__ boh,
                     float* __restrict__ out) {
    extern __shared__ __align__(128) char smem[];
    const uint32_t su = smem_u32(smem);
    const int tid = threadIdx.x;
    const int wid = tid >> 5, lane = tid & 31;
    const int g = lane >> 2, tq = lane & 3;
    const int warp_m = wid >> 2;          // 0..1
    const int warp_n = wid & 3;           // 0..3 == gate
    const int m0 = blockIdx.y * MT;
    const int bx = blockIdx.x;            // n-tile
    const int n0 = bx * 64;

    const __nv_bfloat16* Abase_h = g_Ahi + (size_t)m0 * KTOT;
    const __nv_bfloat16* Abase_l = g_Alo + (size_t)m0 * KTOT;
    const __nv_bfloat16* Wbase_h = g_Whi + (size_t)bx * NPT * KTOT;
    const __nv_bfloat16* Wbase_l = g_Wlo + (size_t)bx * NPT * KTOT;

    float acc[4][8][4];
    #pragma unroll
    for (int a = 0; a < 4; a++)
        #pragma unroll
        for (int b = 0; b < 8; b++)
            #pragma unroll
            for (int c = 0; c < 4; c++) acc[a][b][c] = 0.f;

    // ---- pipeline loads ----
    auto load_stage = [&](int t, int s) {
        const int k0 = t * BK;
        const uint32_t st = su + (uint32_t)s * STG;
        #pragma unroll
        for (int rep = 0; rep < 2; rep++) {                 // A hi/lo: 512 chunks each
            int i = tid + rep * 256;
            int row = i >> 2, cc = i & 3;
            const __nv_bfloat16* sh = Abase_h + (size_t)row * KTOT + k0 + cc * 8;
            const __nv_bfloat16* sl = Abase_l + (size_t)row * KTOT + k0 + cc * 8;
            uint32_t off = (uint32_t)row * ROWB + cc * 16;
            CP_ASYNC16(st + off,        sh);
            CP_ASYNC16(st + ASZ + off,  sl);
        }
        #pragma unroll
        for (int rep = 0; rep < 4; rep++) {                 // B hi/lo: 1024 chunks each
            int i = tid + rep * 256;
            int row = i >> 2, cc = i & 3;
            const __nv_bfloat16* sh = Wbase_h + (size_t)row * KTOT + k0 + cc * 8;
            const __nv_bfloat16* sl = Wbase_l + (size_t)row * KTOT + k0 + cc * 8;
            uint32_t off = (uint32_t)row * ROWB + cc * 16;
            CP_ASYNC16(st + 2 * ASZ + off,        sh);
            CP_ASYNC16(st + 2 * ASZ + BSZ + off,  sl);
        }
        CP_COMMIT();
    };

    load_stage(0, 0);
    load_stage(1, 1);

    // ldmatrix per-lane address components
    const int grp = lane >> 3, lr = lane & 7;
    // A x4: groups -> (row+0,k0),(row+8,k0),(row+0,k+8),(row+8,k+8)
    const uint32_t aRowOff = (uint32_t)(warp_m * 64 + ((grp & 1) << 3) + lr);
    const uint32_t aKoff   = (uint32_t)((grp >> 1) << 4);
    // B x4: groups -> (tile0,k0),(tile0,k+8),(tile1,k0),(tile1,k+8)
    const uint32_t bRowOff = (uint32_t)(warp_n * 64 + ((grp >> 1) << 3) + lr);
    const uint32_t bKoff   = (uint32_t)((grp & 1) << 4);

    #pragma unroll 1
    for (int t = 0; t < NITER; t++) {
        if (t < NITER - 1) CP_WAIT(1); else CP_WAIT(0);
        __syncthreads();
        if (t + 2 < NITER) load_stage(t + 2, (t + 2) % NSTAGE);

        const uint32_t st = su + (uint32_t)(t % NSTAGE) * STG;
        const uint32_t uAh = st, uAl = st + ASZ, uBh = st + 2 * ASZ, uBl = st + 2 * ASZ + BSZ;

        #pragma unroll
        for (int kt = 0; kt < 2; kt++) {
            const uint32_t kb = (uint32_t)(kt * 32);
            uint32_t afh[4][4], afl[4][4], bfh[4][4], bfl[4][4];
            #pragma unroll
            for (int tm = 0; tm < 4; tm++) {
                uint32_t r = (aRowOff + 16 * tm) * ROWB + kb + aKoff;
                ldsm4(afh[tm], uAh + r);
                ldsm4(afl[tm], uAl + r);
            }
            #pragma unroll
            for (int p = 0; p < 4; p++) {
                uint32_t r = (bRowOff + 16 * p) * ROWB + kb + bKoff;
                ldsm4(bfh[p], uBh + r);
                ldsm4(bfl[p], uBl + r);
            }
            #pragma unroll
            for (int tm = 0; tm < 4; tm++)
                #pragma unroll
                for (int tn = 0; tn < 8; tn++) {
                    const uint32_t* bh = &bfh[tn >> 1][(tn & 1) * 2];
                    const uint32_t* bl = &bfl[tn >> 1][(tn & 1) * 2];
                    mma16816(acc[tm][tn], afh[tm], bh);
                    mma16816(acc[tm][tn], afh[tm], bl);
                    mma16816(acc[tm][tn], afl[tm], bh);
                }
        }
    }
    __syncthreads();

    // ---- epilogue: combine 4 gates through smem, fuse LSTM math ----
    // layout: eg[warp_m][gate][64][68] floats ; biases after
    float* eg   = (float*)smem;
    float* bsum = (float*)(smem + 2 * 4 * 64 * 68 * 4);   // 139264
    const uint32_t egBase = (uint32_t)((warp_m * 4 + warp_n) * 64 * 68);

    #pragma unroll
    for (int tm = 0; tm < 4; tm++)
        #pragma unroll
        for (int tn = 0; tn < 8; tn++) {
            uint32_t r0 = egBase + (uint32_t)(16 * tm + g) * 68 + 8 * tn + tq * 2;
            eg[r0]            = acc[tm][tn][0];
            eg[r0 + 1]        = acc[tm][tn][1];
            eg[r0 + 8 * 68]     = acc[tm][tn][2];
            eg[r0 + 8 * 68 + 1] = acc[tm][tn][3];
        }
    if (tid < 64) {
        int n = n0 + tid;
        bsum[tid]       = bix[n] + bih[n];
        bsum[64 + tid]  = bfx[n] + bfh[n];
        bsum[128 + tid] = bcx[n] + bch[n];
        bsum[192 + tid] = box_[n] + boh[n];
    }
    __syncthreads();

    #pragma unroll
    for (int it = 0; it < 32; it++) {
        int idx = tid + it * 256;          // 0..8191
        int row = idx >> 6, col = idx & 63;
        int wm = row >> 6, r = row & 63;
        const float* base = eg + (size_t)wm * 4 * 64 * 68 + (size_t)r * 68 + col;
        float I = base[0]            + bsum[col];
        float F = base[64 * 68]      + bsum[64 + col];
        float G = tanhf(base[2 * 64 * 68] + bsum[128 + col]);
        float O = base[3 * 64 * 68]  + bsum[192 + col];
        size_t go = (size_t)(m0 + row) * HDIM + n0 + col;
        float cn = G * I + c_prev[go] * F;
        out[go] = O * tanhf(cn);
        out[(size_t)BDIM * HDIM + go] = cn;
    }
}

// ---------------- launch ----------------
extern "C" void kernel_launch(void* const* d_in, const int* in_sizes, int n_in,
                              void* d_out, int out_size) {
    const float* x      = (const float*)d_in[0];
    const float* h      = (const float*)d_in[1];
    const float* c_prev = (const float*)d_in[2];
    const float* Wix = (const float*)d_in[3];  const float* bix  = (const float*)d_in[4];
    const float* Wfx = (const float*)d_in[5];  const float* bfx  = (const float*)d_in[6];
    const float* Wcx = (const float*)d_in[7];  const float* bcx  = (const float*)d_in[8];
    const float* Wox = (const float*)d_in[9];  const float* box_ = (const float*)d_in[10];
    const float* Wih = (const float*)d_in[11]; const float* bih  = (const float*)d_in[12];
    const float* Wfh = (const float*)d_in[13]; const float* bfh  = (const float*)d_in[14];
    const float* Wch = (const float*)d_in[15]; const float* bch  = (const float*)d_in[16];
    const float* Woh = (const float*)d_in[17]; const float* boh  = (const float*)d_in[18];
    float* out = (float*)d_out;

    conv_A_kernel<<<BDIM * KTOT / 8 / 256, 256>>>(x, h);
    conv_W_kernel<<<4 * HDIM * KTOT / 8 / 256, 256>>>(Wix, Wfx, Wcx, Wox, Wih, Wfh, Wch, Woh);

    cudaFuncSetAttribute(lstm_mma_kernel, cudaFuncAttributeMaxDynamicSharedMemorySize, SMEM_TOTAL);
    dim3 grid(HDIM / 64, BDIM / MT);   // (16, 128)
    lstm_mma_kernel<<<grid, THREADS, SMEM_TOTAL>>>(c_prev,
        bix, bih, bfx, bfh, bcx, bch, box_, boh, out);
}